// round 17
// baseline (speedup 1.0000x reference)
#include <cuda_runtime.h>
#include <cuda_fp16.h>

#define THREADS 256
#define IT 4                      // i-rows per thread
#define I_TILE (THREADS * IT)     // 1024
#define J_TILE 64
#define MAXB 8192
#define MAXN 16384
#define MAXT (MAXN / J_TILE)

__device__ double   g_partial[MAXB];
__device__ int      g_done = 0;
// per-tile sorted scratch (prep_kernel -> rankloss_kernel)
__device__ float    g_srt_t[MAXN];                 // sorted targets (fp32)
__device__ float    g_srt_E[MAXN];                 // Ej = 2^pjs, sorted
__device__ float    g_pre[MAXT * (J_TILE + 1)];    // prefix sums of sorted pjs
__device__ uint2    g_h2[MAXN];                    // (half2 tj, half2 pjs), sorted

__device__ __forceinline__ float fast_lg2(float x) {
    float r; asm("lg2.approx.f32 %0, %1;" : "=f"(r) : "f"(x)); return r;
}
__device__ __forceinline__ float fast_ex2(float x) {
    float r; asm("ex2.approx.f32 %0, %1;" : "=f"(r) : "f"(x)); return r;
}
__device__ __forceinline__ unsigned h2bits_f(float lo, float hi) {
    __half2 h = __floats2half2_rn(lo, hi);
    return *reinterpret_cast<unsigned*>(&h);
}
// band pair-op (R12-proven): 2 pairs, fp16 sign orientation, fp32 products
__device__ __forceinline__ void pair2(float& prodLo, float& prodHi,
                                      unsigned vt, unsigned ti,
                                      unsigned vp, unsigned pi) {
    asm("{\n\t"
        ".reg .b32 s, a;\n\t"
        ".reg .b16 lo, hi;\n\t"
        ".reg .f32 f0, f1;\n\t"
        "sub.rn.f16x2 s, %2, %3;\n\t"
        "sub.rn.f16x2 a, %4, %5;\n\t"
        "lop3.b32 a, a, s, 0x80008000, 0x78;\n\t"
        "ex2.approx.f16x2 a, a;\n\t"
        "mov.b32 {lo, hi}, a;\n\t"
        "cvt.f32.f16 f0, lo;\n\t"
        "cvt.f32.f16 f1, hi;\n\t"
        "fma.rn.f32 %0, %0, f0, %0;\n\t"
        "fma.rn.f32 %1, %1, f1, %1;\n\t"
        "}"
        : "+f"(prodLo), "+f"(prodHi)
        : "r"(vt), "r"(ti), "r"(vp), "r"(pi));
}

// ---- prep: per 64-j tile, sort by target; emit sorted t, Ej=2^pjs, prefix ----
__global__ __launch_bounds__(J_TILE)
void prep_kernel(const float* __restrict__ P, const float* __restrict__ T, int n) {
    const int tile = blockIdx.x;
    const int tid  = threadIdx.x;
    const float LOG2E = 1.4426950408889634f;
    const float INF   = __int_as_float(0x7F800000);

    __shared__ float st[J_TILE];
    __shared__ float sp[J_TILE];
    __shared__ float scan[J_TILE];

    int jg = tile * J_TILE + tid;
    if (jg < n) { st[tid] = T[jg]; sp[tid] = P[jg] * LOG2E; }
    else        { st[tid] = INF;   sp[tid] = -INF; }  // pad sorts last, Ej=0
    __syncthreads();

    for (int k = 2; k <= J_TILE; k <<= 1) {
        for (int half = k >> 1; half > 0; half >>= 1) {
            int partner = tid ^ half;
            if (partner > tid) {
                bool up = ((tid & k) == 0);
                float t1 = st[tid], t2 = st[partner];
                if ((t1 > t2) == up) {
                    st[tid] = t2; st[partner] = t1;
                    float p1 = sp[tid], p2 = sp[partner];
                    sp[tid] = p2; sp[partner] = p1;
                }
            }
            __syncthreads();
        }
    }

    float v = (st[tid] < INF) ? sp[tid] : 0.0f;   // pads contribute 0
    scan[tid] = v;
    __syncthreads();
    #pragma unroll
    for (int off = 1; off < J_TILE; off <<= 1) {
        float add = (tid >= off) ? scan[tid - off] : 0.0f;
        __syncthreads();
        scan[tid] += add;
        __syncthreads();
    }

    int og = tile * J_TILE + tid;
    float tj = st[tid], pj = sp[tid];
    g_srt_t[og] = tj;
    g_srt_E[og] = fast_ex2(pj);                   // 2^-inf = 0 for pads
    g_h2[og]    = make_uint2(h2bits_f(tj, tj), h2bits_f(pj, pj));
    if (tid == 0) g_pre[tile * (J_TILE + 1)] = 0.0f;
    g_pre[tile * (J_TILE + 1) + tid + 1] = scan[tid];
}

// Dense blocks: acc += lg2 prod(1 + Ej*Fi) over all pairs (ZERO MUFU/pair),
// then exact correction acc -= sum_{tj<ti}(pjs-pis) = spre[m] - m*pis.
// Band blocks: full cross, fp16 sign path; each pair twice + diagonal 1.0:
// partial = 0.5*(sum - jcount). Count analytic: n(n-1)/2.
__global__ __launch_bounds__(THREADS, 4)
void rankloss_kernel(const float* __restrict__ P, const float* __restrict__ T,
                     float* __restrict__ out, int n, int NTI, int NTJ,
                     double inv_neg_count) {
    const int tid = threadIdx.x;
    const int nb  = gridDim.x;

    int b = blockIdx.x, I = 0, J = 0;
    {
        int rem = b;
        for (int ii = 0; ii < NTI; ++ii) {
            int jmin = (ii * I_TILE) / J_TILE;
            int cntI = NTJ - jmin;
            if (rem < cntI) { I = ii; J = jmin + rem; break; }
            rem -= cntI;
        }
    }
    const int I0 = I * I_TILE;
    const int J0 = J * J_TILE;
    const bool band = (J0 < I0 + I_TILE);

    __shared__ float  st[J_TILE];        // sorted tj (dense: search)
    __shared__ float  sE[J_TILE];        // Ej = 2^pjs (dense)
    __shared__ float  spre[J_TILE + 1];  // prefix sums (dense)
    __shared__ uint2  sjv[J_TILE];       // half2 packs (band)
    __shared__ double sred[THREADS];

    const float LOG2E = 1.4426950408889634f;
    const float INF   = __int_as_float(0x7F800000);

    if (tid < J_TILE) {
        st[tid]  = g_srt_t[J0 + tid];
        sE[tid]  = g_srt_E[J0 + tid];
        sjv[tid] = g_h2[J0 + tid];
    }
    if (tid < J_TILE + 1) spre[tid] = g_pre[(J0 / J_TILE) * (J_TILE + 1) + tid];

    float tiv[IT], piv[IT];
    #pragma unroll
    for (int r = 0; r < IT; ++r) {
        int ig = I0 + r * THREADS + tid;
        if (ig < n) { tiv[r] = T[ig]; piv[r] = P[ig] * LOG2E; }
        else        { tiv[r] = -INF;  piv[r] = INF; }  // Fi=0, m=0 -> no contrib
    }
    __syncthreads();

    float acc = 0.0f;

    if (!band) {
        float Fi0 = fast_ex2(-piv[0]);
        float Fi1 = fast_ex2(-piv[1]);
        float Fi2 = fast_ex2(-piv[2]);
        float Fi3 = fast_ex2(-piv[3]);

        // m_r = #(tj < ti) on sorted st (exact fp32)
        int mI[IT];
        #pragma unroll
        for (int r = 0; r < IT; ++r) {
            int m = 0;
            #pragma unroll
            for (int step = 32; step >= 1; step >>= 1)
                if (st[m + step - 1] < tiv[r]) m += step;
            mI[r] = m;
        }

        #pragma unroll 1
        for (int j = 0; j < J_TILE; j += 8) {
            float prod0 = 1.0f, prod1 = 1.0f, prod2 = 1.0f, prod3 = 1.0f;
            #pragma unroll
            for (int jj = 0; jj < 8; ++jj) {
                float Ej = sE[j + jj];          // broadcast LDS.32
                float u0 = Ej * Fi0;
                float u1 = Ej * Fi1;
                float u2 = Ej * Fi2;
                float u3 = Ej * Fi3;
                prod0 = fmaf(prod0, u0, prod0); // *(1 + Ej*Fi)
                prod1 = fmaf(prod1, u1, prod1);
                prod2 = fmaf(prod2, u2, prod2);
                prod3 = fmaf(prod3, u3, prod3);
            }
            acc += fast_lg2(prod0);
            acc += fast_lg2(prod1);
            acc += fast_lg2(prod2);
            acc += fast_lg2(prod3);
        }

        // exact correction: acc -= sum_{tj<ti} (pjs - pis)
        acc -= spre[mI[0]] - (float)mI[0] * piv[0];
        acc -= spre[mI[1]] - (float)mI[1] * piv[1];
        acc -= spre[mI[2]] - (float)mI[2] * piv[2];
        acc -= spre[mI[3]] - (float)mI[3] * piv[3];
    } else {
        const unsigned ti01 = h2bits_f(tiv[0], tiv[1]);
        const unsigned ti23 = h2bits_f(tiv[2], tiv[3]);
        const unsigned pi01 = h2bits_f(piv[0], piv[1]);
        const unsigned pi23 = h2bits_f(piv[2], piv[3]);

        #pragma unroll 1
        for (int j = 0; j < J_TILE; j += 8) {
            float prod0 = 1.0f, prod1 = 1.0f, prod2 = 1.0f, prod3 = 1.0f;
            #pragma unroll
            for (int jj = 0; jj < 8; ++jj) {
                uint2 v = sjv[j + jj];
                pair2(prod0, prod1, v.x, ti01, v.y, pi01);
                pair2(prod2, prod3, v.x, ti23, v.y, pi23);
            }
            acc += fast_lg2(prod0);
            acc += fast_lg2(prod1);
            acc += fast_lg2(prod2);
            acc += fast_lg2(prod3);
        }
    }

    // block reduction (fixed order -> deterministic)
    sred[tid] = (double)acc;
    __syncthreads();
    #pragma unroll
    for (int s = THREADS / 2; s > 0; s >>= 1) {
        if (tid < s) sred[tid] += sred[tid + s];
        __syncthreads();
    }
    if (tid == 0) {
        double bsum = sred[0];
        if (band) {
            int jcount = min(J_TILE, n - J0);
            bsum = 0.5 * (bsum - (double)jcount);
        }
        g_partial[blockIdx.x] = bsum;
    }

    // last-block finalize
    __shared__ int is_last;
    if (tid == 0) {
        __threadfence();
        int prev = atomicAdd(&g_done, 1);
        is_last = (prev == nb - 1) ? 1 : 0;
    }
    __syncthreads();
    if (is_last) {
        __threadfence();
        double s = 0.0;
        for (int i = tid; i < nb; i += THREADS) s += g_partial[i];
        sred[tid] = s;
        __syncthreads();
        #pragma unroll
        for (int k = THREADS / 2; k > 0; k >>= 1) {
            if (tid < k) sred[tid] += sred[tid + k];
            __syncthreads();
        }
        if (tid == 0) {
            out[0] = (float)(sred[0] * inv_neg_count);
            g_done = 0;
        }
    }
}

extern "C" void kernel_launch(void* const* d_in, const int* in_sizes, int n_in,
                              void* d_out, int out_size) {
    const float* predictions = (const float*)d_in[0];
    const float* targets     = (const float*)d_in[1];
    const int n = in_sizes[0];

    const int NTI = (n + I_TILE - 1) / I_TILE;   // 8 for n=8192
    const int NTJ = (n + J_TILE - 1) / J_TILE;   // 128
    int nb = 0;
    for (int ii = 0; ii < NTI; ++ii) {
        int jmin = (ii * I_TILE) / J_TILE;
        nb += NTJ - jmin;                        // 576 for n=8192
    }
    const double count = 0.5 * (double)n * (double)(n - 1);
    const double inv_neg_count = -0.6931471805599453 / count;

    prep_kernel<<<NTJ, J_TILE>>>(predictions, targets, n);
    rankloss_kernel<<<nb, THREADS>>>(predictions, targets, (float*)d_out,
                                     n, NTI, NTJ, inv_neg_count);
}